// round 4
// baseline (speedup 1.0000x reference)
#include <cuda_runtime.h>
#include <math.h>
#include <stdint.h>
#include <stddef.h>

#define BB 2
#define NN 2048
#define EE 256
#define HH 4
#define DKK 64
#define MTOT (BB*NN)

#define TQ 64
#define TK 64

// 1/sqrt(64) * log2(e): scores precomputed in log2 domain for ex2-softmax
#define QSCALE 0.1803368801111204f

typedef unsigned long long u64;

__device__ __forceinline__ u64 ffma2(u64 a, u64 b, u64 c) {
    u64 d; asm("fma.rn.f32x2 %0, %1, %2, %3;" : "=l"(d) : "l"(a), "l"(b), "l"(c)); return d;
}
__device__ __forceinline__ u64 fmul2(u64 a, u64 b) {
    u64 d; asm("mul.rn.f32x2 %0, %1, %2;" : "=l"(d) : "l"(a), "l"(b)); return d;
}
__device__ __forceinline__ u64 pack2f(float x, float y) {
    u64 r; asm("mov.b64 %0, {%1, %2};" : "=l"(r) : "f"(x), "f"(y)); return r;
}
__device__ __forceinline__ float hadd2(u64 a) {
    float x, y; asm("mov.b64 {%0, %1}, %2;" : "=f"(x), "=f"(y) : "l"(a)); return x + y;
}
__device__ __forceinline__ float ex2f(float x) {
    float r; asm("ex2.approx.f32 %0, %1;" : "=f"(r) : "f"(x)); return r;
}

// Scratch
__device__ float g_Q[BB*HH*NN*DKK];
__device__ float g_K[BB*HH*NN*DKK];
__device__ float g_V[BB*HH*NN*DKK];
__device__ float g_C[BB*NN*EE];
__device__ float g_WT[3*HH*DKK*EE];   // [(mat*4+h)*64 + e][256 d]  (d contiguous)

// pair-column swizzle used by all B-operand smem tiles (row c, d-pair dp)
__device__ __forceinline__ int pswz(int dp, int c) { return (dp + c + (c >> 5)) & 31; }

// ---------------------------------------------------------------------------
// Transpose Wq/Wk/Wv into d-contiguous layout g_WT.
// ---------------------------------------------------------------------------
__global__ void __launch_bounds__(256) wtrans_kernel(
    const float* __restrict__ Wq, const float* __restrict__ Wk,
    const float* __restrict__ Wv)
{
    int idx = blockIdx.x * 256 + threadIdx.x;      // [0, 196608)
    int mat = idx >> 16;
    int rem = idx & 65535;                          // h*16384 + d*64 + e
    const float* src = (mat == 0) ? Wq : (mat == 1) ? Wk : Wv;
    int h = rem >> 14, d = (rem >> 6) & 255, e = rem & 63;
    g_WT[((mat * HH + h) * DKK + e) * EE + d] = src[rem];
}

// ---------------------------------------------------------------------------
// QKV projection as 64x64-tile FFMA2 GEMM. Grid = (MTOT/64, 12).
// blockIdx.y: mat = y>>2, h = y&3. 256 thr = 16(tx) x 16(ty), 4x4 micro-tiles
// packed over the reduction (d) dimension.
// ---------------------------------------------------------------------------
__global__ void __launch_bounds__(256) qkv_kernel(const float* __restrict__ X)
{
    __shared__ float As[64][64];     // X rows, d chunk
    __shared__ float Bs[64 * 64];    // weight cols (e), pair-swizzled d

    const int t = threadIdx.x;
    const int tx = t & 15, ty = t >> 4;
    const int m0 = blockIdx.x * 64;
    const int y  = blockIdx.y;
    const int cbase = y * 64;        // row offset in g_WT

    u64 acc2[4][4];
    #pragma unroll
    for (int i = 0; i < 4; i++)
        #pragma unroll
        for (int j = 0; j < 4; j++) acc2[i][j] = 0ull;

    for (int k0 = 0; k0 < EE; k0 += 64) {
        for (int i4 = t * 4; i4 < 64 * 64; i4 += 1024) {
            int r = i4 >> 6, d0 = i4 & 63;
            *(float4*)&As[r][d0] = *(const float4*)&X[(size_t)(m0 + r) * EE + k0 + d0];
            float4 w = *(const float4*)&g_WT[(size_t)(cbase + r) * EE + k0 + d0];
            int kp = d0 >> 1;
            *(float2*)&Bs[r * 64 + pswz(kp,     r) * 2] = make_float2(w.x, w.y);
            *(float2*)&Bs[r * 64 + pswz(kp + 1, r) * 2] = make_float2(w.z, w.w);
        }
        __syncthreads();

        #pragma unroll 4
        for (int dp = 0; dp < 32; dp++) {
            u64 a2[4], b2[4];
            #pragma unroll
            for (int i = 0; i < 4; i++) a2[i] = *(const u64*)&As[ty * 4 + i][dp * 2];
            #pragma unroll
            for (int j = 0; j < 4; j++) {
                int c = tx * 4 + j;
                b2[j] = *(const u64*)&Bs[c * 64 + pswz(dp, c) * 2];
            }
            #pragma unroll
            for (int i = 0; i < 4; i++)
                #pragma unroll
                for (int j = 0; j < 4; j++)
                    acc2[i][j] = ffma2(a2[i], b2[j], acc2[i][j]);
        }
        __syncthreads();
    }

    const int mat = y >> 2, h = y & 3;
    float* dst = (mat == 0) ? g_Q : (mat == 1) ? g_K : g_V;
    const float mult = (mat == 0) ? QSCALE : 1.0f;
    #pragma unroll
    for (int i = 0; i < 4; i++) {
        int m = m0 + ty * 4 + i;
        int b = m >> 11, n = m & 2047;
        float4 o4;
        o4.x = hadd2(acc2[i][0]) * mult;
        o4.y = hadd2(acc2[i][1]) * mult;
        o4.z = hadd2(acc2[i][2]) * mult;
        o4.w = hadd2(acc2[i][3]) * mult;
        *(float4*)&dst[((size_t)(b * HH + h) * NN + n) * DKK + tx * 4] = o4;
    }
}

// ---------------------------------------------------------------------------
// Flash attention, FFMA2 everywhere.
//   S = Q K^T packed over d  (K in KP: row kc, paircol pswz(dp,kc))
//   softmax in log2 domain (ex2.approx)
//   P stored: row qr, paircol (kp+qr)&31  (kc pairs contiguous)
//   O += P V packed over kc  (V transposed: Vt[d][kc], paircol (kp+(d>>2))&31)
//   oacc packed over kc parity; halves summed only at the epilogue.
// ---------------------------------------------------------------------------
__global__ void __launch_bounds__(256) attn_kernel(const int* __restrict__ Adj)
{
    __shared__ float Qs[TQ][DKK];    // 16 KB
    __shared__ float KP[TK * DKK];   // 16 KB : K tile, then P tile
    __shared__ float Vt[DKK * TK];   // 16 KB : V transposed [d][kc]

    const int t  = threadIdx.x;
    const int tx = t & 15, ty = t >> 4;
    const int q0 = blockIdx.x * TQ;
    const int bh = blockIdx.y;
    const int b  = bh >> 2;

    const float* Qg = g_Q + ((size_t)bh * NN + q0) * DKK;
    for (int i4 = t * 4; i4 < TQ * DKK; i4 += 1024) {
        int r = i4 >> 6, d = i4 & 63;
        *(float4*)&Qs[r][d] = *(const float4*)&Qg[(size_t)r * DKK + d];
    }

    float m_[4], l_[4];
    u64 oacc2[4][4];
    #pragma unroll
    for (int i = 0; i < 4; i++) {
        m_[i] = -1e30f; l_[i] = 0.f;
        #pragma unroll
        for (int j = 0; j < 4; j++) oacc2[i][j] = 0ull;
    }

    const int* Arow = Adj + ((size_t)(b * NN) + q0 + ty * 4) * NN;
    __syncthreads();

    for (int k0 = 0; k0 < NN; k0 += TK) {
        const float* Kg = g_K + ((size_t)bh * NN + k0) * DKK;
        const float* Vg = g_V + ((size_t)bh * NN + k0) * DKK;
        for (int i4 = t * 4; i4 < TK * DKK; i4 += 1024) {
            int kc = i4 >> 6, d0 = i4 & 63, kp = d0 >> 1;
            float4 kv = *(const float4*)&Kg[(size_t)kc * DKK + d0];
            *(float2*)&KP[kc * 64 + pswz(kp,     kc) * 2] = make_float2(kv.x, kv.y);
            *(float2*)&KP[kc * 64 + pswz(kp + 1, kc) * 2] = make_float2(kv.z, kv.w);
            float4 vv = *(const float4*)&Vg[(size_t)kc * DKK + d0];
            int vcol = (((kc >> 1) + (d0 >> 2)) & 31) * 2 + (kc & 1);
            Vt[(d0 + 0) * 64 + vcol] = vv.x;
            Vt[(d0 + 1) * 64 + vcol] = vv.y;
            Vt[(d0 + 2) * 64 + vcol] = vv.z;
            Vt[(d0 + 3) * 64 + vcol] = vv.w;
        }
        __syncthreads();

        // ---- S = Q K^T (packed over d) ----
        u64 s2[4][4];
        #pragma unroll
        for (int i = 0; i < 4; i++)
            #pragma unroll
            for (int j = 0; j < 4; j++) s2[i][j] = 0ull;

        #pragma unroll 4
        for (int dp = 0; dp < 32; dp++) {
            u64 q2[4], k2[4];
            #pragma unroll
            for (int i = 0; i < 4; i++) q2[i] = *(const u64*)&Qs[ty * 4 + i][dp * 2];
            #pragma unroll
            for (int j = 0; j < 4; j++) {
                int kc = tx * 4 + j;
                k2[j] = *(const u64*)&KP[kc * 64 + pswz(dp, kc) * 2];
            }
            #pragma unroll
            for (int i = 0; i < 4; i++)
                #pragma unroll
                for (int j = 0; j < 4; j++)
                    s2[i][j] = ffma2(q2[i], k2[j], s2[i][j]);
        }

        float s_[4][4];
        #pragma unroll
        for (int i = 0; i < 4; i++)
            #pragma unroll
            for (int j = 0; j < 4; j++) s_[i][j] = hadd2(s2[i][j]);

        // ---- adjacency mask ----
        #pragma unroll
        for (int i = 0; i < 4; i++) {
            const int4 am = *(const int4*)&Arow[(size_t)i * NN + k0 + tx * 4];
            if (am.x <= 0) s_[i][0] = -1e30f;
            if (am.y <= 0) s_[i][1] = -1e30f;
            if (am.z <= 0) s_[i][2] = -1e30f;
            if (am.w <= 0) s_[i][3] = -1e30f;
        }

        __syncthreads();   // done reading K; KP about to become P

        // ---- online softmax (base-2), write P pairs ----
        #pragma unroll
        for (int i = 0; i < 4; i++) {
            float mx = fmaxf(fmaxf(s_[i][0], s_[i][1]), fmaxf(s_[i][2], s_[i][3]));
            mx = fmaxf(mx, __shfl_xor_sync(0xffffffffu, mx, 8, 16));
            mx = fmaxf(mx, __shfl_xor_sync(0xffffffffu, mx, 4, 16));
            mx = fmaxf(mx, __shfl_xor_sync(0xffffffffu, mx, 2, 16));
            mx = fmaxf(mx, __shfl_xor_sync(0xffffffffu, mx, 1, 16));
            float mn = fmaxf(m_[i], mx);
            float alpha = ex2f(m_[i] - mn);
            float rs = 0.f;
            #pragma unroll
            for (int j = 0; j < 4; j++) {
                float p = ex2f(s_[i][j] - mn);
                s_[i][j] = p;
                rs += p;
            }
            rs += __shfl_xor_sync(0xffffffffu, rs, 8, 16);
            rs += __shfl_xor_sync(0xffffffffu, rs, 4, 16);
            rs += __shfl_xor_sync(0xffffffffu, rs, 2, 16);
            rs += __shfl_xor_sync(0xffffffffu, rs, 1, 16);
            l_[i] = l_[i] * alpha + rs;
            m_[i] = mn;
            u64 alpha2 = pack2f(alpha, alpha);
            #pragma unroll
            for (int j = 0; j < 4; j++) oacc2[i][j] = fmul2(oacc2[i][j], alpha2);
            int qr = ty * 4 + i;
            *(float2*)&KP[qr * 64 + ((tx * 2     + qr) & 31) * 2] = make_float2(s_[i][0], s_[i][1]);
            *(float2*)&KP[qr * 64 + ((tx * 2 + 1 + qr) & 31) * 2] = make_float2(s_[i][2], s_[i][3]);
        }
        __syncthreads();   // P ready

        // ---- O += P V (packed over kc pairs) ----
        #pragma unroll 4
        for (int kp = 0; kp < 32; kp++) {
            u64 p2[4], v2[4];
            #pragma unroll
            for (int i = 0; i < 4; i++) {
                int qr = ty * 4 + i;
                p2[i] = *(const u64*)&KP[qr * 64 + ((kp + qr) & 31) * 2];
            }
            #pragma unroll
            for (int j = 0; j < 4; j++) {
                int d = tx * 4 + j;
                v2[j] = *(const u64*)&Vt[d * 64 + ((kp + (d >> 2)) & 31) * 2];
            }
            #pragma unroll
            for (int i = 0; i < 4; i++)
                #pragma unroll
                for (int j = 0; j < 4; j++)
                    oacc2[i][j] = ffma2(p2[i], v2[j], oacc2[i][j]);
        }
        __syncthreads();   // done with KP/Vt before next fill
    }

    const int h = bh & 3;
    #pragma unroll
    for (int i = 0; i < 4; i++) {
        float inv = 1.f / l_[i];
        int q = q0 + ty * 4 + i;
        float4 o4;
        o4.x = hadd2(oacc2[i][0]) * inv;
        o4.y = hadd2(oacc2[i][1]) * inv;
        o4.z = hadd2(oacc2[i][2]) * inv;
        o4.w = hadd2(oacc2[i][3]) * inv;
        *(float4*)&g_C[((size_t)(b * NN) + q) * EE + h * DKK + tx * 4] = o4;
    }
}

// ---------------------------------------------------------------------------
// Output projection: out = C @ Wo^T + bo as 64x64-tile FFMA2 GEMM.
// Wo rows are already d-contiguous. Grid = (MTOT/64, 4).
// ---------------------------------------------------------------------------
__global__ void __launch_bounds__(256) out_kernel(
    const float* __restrict__ Wo, const float* __restrict__ bo,
    float* __restrict__ out)
{
    __shared__ float As[64][64];
    __shared__ float Bs[64 * 64];

    const int t = threadIdx.x;
    const int tx = t & 15, ty = t >> 4;
    const int m0 = blockIdx.x * 64;
    const int o0 = blockIdx.y * 64;

    u64 acc2[4][4];
    #pragma unroll
    for (int i = 0; i < 4; i++)
        #pragma unroll
        for (int j = 0; j < 4; j++) acc2[i][j] = 0ull;

    for (int k0 = 0; k0 < EE; k0 += 64) {
        for (int i4 = t * 4; i4 < 64 * 64; i4 += 1024) {
            int r = i4 >> 6, d0 = i4 & 63;
            *(float4*)&As[r][d0] = *(const float4*)&g_C[(size_t)(m0 + r) * EE + k0 + d0];
            float4 w = *(const float4*)&Wo[(size_t)(o0 + r) * EE + k0 + d0];
            int kp = d0 >> 1;
            *(float2*)&Bs[r * 64 + pswz(kp,     r) * 2] = make_float2(w.x, w.y);
            *(float2*)&Bs[r * 64 + pswz(kp + 1, r) * 2] = make_float2(w.z, w.w);
        }
        __syncthreads();

        #pragma unroll 4
        for (int dp = 0; dp < 32; dp++) {
            u64 a2[4], b2[4];
            #pragma unroll
            for (int i = 0; i < 4; i++) a2[i] = *(const u64*)&As[ty * 4 + i][dp * 2];
            #pragma unroll
            for (int j = 0; j < 4; j++) {
                int c = tx * 4 + j;
                b2[j] = *(const u64*)&Bs[c * 64 + pswz(dp, c) * 2];
            }
            #pragma unroll
            for (int i = 0; i < 4; i++)
                #pragma unroll
                for (int j = 0; j < 4; j++)
                    acc2[i][j] = ffma2(a2[i], b2[j], acc2[i][j]);
        }
        __syncthreads();
    }

    float4 bv = *(const float4*)&bo[o0 + tx * 4];
    #pragma unroll
    for (int i = 0; i < 4; i++) {
        int m = m0 + ty * 4 + i;
        float4 o4;
        o4.x = hadd2(acc2[i][0]) + bv.x;
        o4.y = hadd2(acc2[i][1]) + bv.y;
        o4.z = hadd2(acc2[i][2]) + bv.z;
        o4.w = hadd2(acc2[i][3]) + bv.w;
        *(float4*)&out[(size_t)m * EE + o0 + tx * 4] = o4;
    }
}

// ---------------------------------------------------------------------------
extern "C" void kernel_launch(void* const* d_in, const int* in_sizes, int n_in,
                              void* d_out, int out_size)
{
    const float* X   = (const float*)d_in[0];
    const int*   Adj = (const int*)  d_in[1];
    const float* Wq  = (const float*)d_in[2];
    const float* Wk  = (const float*)d_in[3];
    const float* Wv  = (const float*)d_in[4];
    const float* Wo  = (const float*)d_in[5];
    const float* bo  = (const float*)d_in[6];
    float* out = (float*)d_out;

    wtrans_kernel<<<768, 256>>>(Wq, Wk, Wv);
    qkv_kernel<<<dim3(MTOT / 64, 12), 256>>>(X);
    attn_kernel<<<dim3(NN / TQ, BB * HH), 256>>>(Adj);
    out_kernel<<<dim3(MTOT / 64, 4), 256>>>(Wo, bo, out);
}

// round 5
// speedup vs baseline: 2.0183x; 2.0183x over previous
#include <cuda_runtime.h>
#include <cuda_bf16.h>
#include <math.h>
#include <stdint.h>
#include <stddef.h>

#define BB 2
#define NN 2048
#define EE 256
#define HH 4
#define DKK 64
#define MTOT (BB*NN)

// 1/sqrt(64) * log2(e): scores produced in log2 domain for ex2-softmax
#define QSCALE 0.1803368801111204f

typedef unsigned int u32;
typedef unsigned long long u64;

__device__ __forceinline__ float ex2f(float x) {
    float r; asm("ex2.approx.f32 %0, %1;" : "=f"(r) : "f"(x)); return r;
}

// Scratch
__device__ float g_Q[BB*HH*NN*DKK];
__device__ float g_K[BB*HH*NN*DKK];
__device__ float g_V[BB*HH*NN*DKK];
__device__ float g_C[BB*NN*EE];
__device__ float g_WoT[EE*EE];
__device__ u32   g_mask[BB*NN*NN/32];   // adjacency bitmask, 1 MB

// bf16 hi/lo split of a pair of floats, packed low-half = first element
__device__ __forceinline__ void split2(float x, float y, u32& hi, u32& lo) {
    __nv_bfloat16 hx = __float2bfloat16(x), hy = __float2bfloat16(y);
    float rx = x - __bfloat162float(hx);
    float ry = y - __bfloat162float(hy);
    __nv_bfloat162 H = __halves2bfloat162(hx, hy);
    __nv_bfloat162 L = __halves2bfloat162(__float2bfloat16(rx), __float2bfloat16(ry));
    hi = *(u32*)&H; lo = *(u32*)&L;
}

#define MMA(d, a, b0_, b1_) asm volatile( \
    "mma.sync.aligned.m16n8k16.row.col.f32.bf16.bf16.f32 " \
    "{%0,%1,%2,%3}, {%4,%5,%6,%7}, {%8,%9}, {%0,%1,%2,%3};" \
    : "+f"(d[0]), "+f"(d[1]), "+f"(d[2]), "+f"(d[3]) \
    : "r"(a[0]), "r"(a[1]), "r"(a[2]), "r"(a[3]), "r"(b0_), "r"(b1_))

// ---------------------------------------------------------------------------
// Adjacency -> bitmask (ballot). One warp per 32-entry word.
// ---------------------------------------------------------------------------
__global__ void __launch_bounds__(256) mask_kernel(const int* __restrict__ Adj)
{
    int gid  = blockIdx.x * 256 + threadIdx.x;
    int word = gid >> 5, lane = gid & 31;
    int v = Adj[(size_t)word * 32 + lane];
    u32 m = __ballot_sync(0xffffffffu, v > 0);
    if (lane == 0) g_mask[word] = m;
}

// ---------------------------------------------------------------------------
// Kernel A: fused Q/K/V projection (proven R3 scalar fp32 version).
// Q pre-scaled by QSCALE (log2-domain scores).
// ---------------------------------------------------------------------------
__global__ void __launch_bounds__(256) qkv_kernel(
    const float* __restrict__ X, const float* __restrict__ Wq,
    const float* __restrict__ Wk, const float* __restrict__ Wv)
{
    __shared__ float xs[8][EE];
    const int m0 = blockIdx.x * 8;
    const int t  = threadIdx.x;

    for (int i = t * 4; i < 8 * EE; i += 256 * 4) {
        int r = i >> 8, d = i & 255;
        *(float4*)&xs[r][d] = *(const float4*)&X[(size_t)(m0 + r) * EE + d];
    }
    __syncthreads();

    const int h = t >> 6, e = t & 63;
    const float* wq = Wq + (size_t)h * EE * DKK + e;
    const float* wk = Wk + (size_t)h * EE * DKK + e;
    const float* wv = Wv + (size_t)h * EE * DKK + e;

    float aq[8], ak[8], av[8];
    #pragma unroll
    for (int r = 0; r < 8; r++) { aq[r] = 0.f; ak[r] = 0.f; av[r] = 0.f; }

    #pragma unroll 2
    for (int d = 0; d < EE; d++) {
        float q_ = wq[d * DKK];
        float k_ = wk[d * DKK];
        float v_ = wv[d * DKK];
        #pragma unroll
        for (int r = 0; r < 8; r++) {
            float x_ = xs[r][d];
            aq[r] = fmaf(x_, q_, aq[r]);
            ak[r] = fmaf(x_, k_, ak[r]);
            av[r] = fmaf(x_, v_, av[r]);
        }
    }

    #pragma unroll
    for (int r = 0; r < 8; r++) {
        int m = m0 + r;
        int b = m >> 11, n = m & 2047;
        size_t base = ((size_t)(b * HH + h) * NN + n) * DKK + e;
        g_Q[base] = aq[r] * QSCALE;
        g_K[base] = ak[r];
        g_V[base] = av[r];
    }
}

// ---------------------------------------------------------------------------
// Kernel B: flash attention on tensor cores (bf16x3 mma, static-offset softmax).
// Block = 256 thr (8 warps), warp w owns q rows [w*16, w*16+16). TQ=128, TK=64.
// Grid = (NN/128, B*H) = (16, 8).
//   S = Q K^T : A = Q frags (registers, whole kernel), B from Kh/Kl smem.
//   softmax  : p = mask ? ex2(s) : 0; l accumulated per-thread (no max, no rescale).
//   PV       : A = p frags (C-frag layout == A-frag layout identity), B from VtH/VtL.
// Smem rows padded to 72 bf16 -> conflict-free 32-bit fragment loads.
// ---------------------------------------------------------------------------
#define KPAD 72

__global__ void __launch_bounds__(256) attn_kernel()
{
    __shared__ __nv_bfloat16 Kh[64*KPAD], Kl[64*KPAD];
    __shared__ __nv_bfloat16 Vth[64*KPAD], Vtl[64*KPAD];

    const int t = threadIdx.x;
    const int w = t >> 5, lane = t & 31;
    const int gq = lane >> 2;      // row-in-frag 0..7
    const int q4 = lane & 3;       // col group
    const int q0 = blockIdx.x * 128;
    const int bh = blockIdx.y;
    const int b  = bh >> 2, h = bh & 3;

    const int r0 = q0 + w * 16 + gq;   // this thread's rows: r0, r0+8

    // ---- Q fragments in registers (hi/lo bf16), for all 4 k-chunks ----
    u32 qh[4][4], ql[4][4];
    {
        const float* Qb = g_Q + (size_t)bh * NN * DKK;
        #pragma unroll
        for (int kc = 0; kc < 4; kc++) {
            int c = kc * 16 + q4 * 2;
            float2 x0 = *(const float2*)&Qb[(size_t)(r0    ) * DKK + c    ];
            float2 x1 = *(const float2*)&Qb[(size_t)(r0 + 8) * DKK + c    ];
            float2 x2 = *(const float2*)&Qb[(size_t)(r0    ) * DKK + c + 8];
            float2 x3 = *(const float2*)&Qb[(size_t)(r0 + 8) * DKK + c + 8];
            split2(x0.x, x0.y, qh[kc][0], ql[kc][0]);
            split2(x1.x, x1.y, qh[kc][1], ql[kc][1]);
            split2(x2.x, x2.y, qh[kc][2], ql[kc][2]);
            split2(x3.x, x3.y, qh[kc][3], ql[kc][3]);
        }
    }

    float o[8][4];
    #pragma unroll
    for (int nt = 0; nt < 8; nt++)
        #pragma unroll
        for (int j = 0; j < 4; j++) o[nt][j] = 0.f;
    float l0 = 0.f, l1 = 0.f;

    const u64* mr0 = (const u64*)g_mask + ((size_t)(b * NN + r0    )) * (NN / 64);
    const u64* mr1 = (const u64*)g_mask + ((size_t)(b * NN + r0 + 8)) * (NN / 64);

    for (int k0 = 0; k0 < NN; k0 += 64) {
        __syncthreads();   // previous tile fully consumed

        // ---- fill K (row-major) and V^T tiles, hi/lo split ----
        const float* Kg = g_K + ((size_t)bh * NN + k0) * DKK;
        const float* Vg = g_V + ((size_t)bh * NN + k0) * DKK;
        #pragma unroll
        for (int i4 = t * 4; i4 < 64 * DKK; i4 += 1024) {
            int kc = i4 >> 6, d = i4 & 63;
            float4 kv = *(const float4*)&Kg[(size_t)kc * DKK + d];
            u32 h0, l0_, h1, l1_;
            split2(kv.x, kv.y, h0, l0_);
            split2(kv.z, kv.w, h1, l1_);
            *(u32*)&Kh[kc * KPAD + d    ] = h0;
            *(u32*)&Kh[kc * KPAD + d + 2] = h1;
            *(u32*)&Kl[kc * KPAD + d    ] = l0_;
            *(u32*)&Kl[kc * KPAD + d + 2] = l1_;

            float4 vv = *(const float4*)&Vg[(size_t)kc * DKK + d];
            float vs[4] = {vv.x, vv.y, vv.z, vv.w};
            #pragma unroll
            for (int j = 0; j < 4; j++) {
                __nv_bfloat16 vh = __float2bfloat16(vs[j]);
                Vth[(d + j) * KPAD + kc] = vh;
                Vtl[(d + j) * KPAD + kc] = __float2bfloat16(vs[j] - __bfloat162float(vh));
            }
        }
        __syncthreads();

        // ---- S = Q K^T ----
        float s[8][4];
        #pragma unroll
        for (int nt = 0; nt < 8; nt++)
            #pragma unroll
            for (int j = 0; j < 4; j++) s[nt][j] = 0.f;

        #pragma unroll
        for (int kc = 0; kc < 4; kc++) {
            #pragma unroll
            for (int nt = 0; nt < 8; nt++) {
                int rowK = nt * 8 + gq;
                int cc = kc * 16 + q4 * 2;
                u32 bh0 = *(const u32*)&Kh[rowK * KPAD + cc];
                u32 bh1 = *(const u32*)&Kh[rowK * KPAD + cc + 8];
                u32 bl0 = *(const u32*)&Kl[rowK * KPAD + cc];
                u32 bl1 = *(const u32*)&Kl[rowK * KPAD + cc + 8];
                MMA(s[nt], qh[kc], bh0, bh1);
                MMA(s[nt], qh[kc], bl0, bl1);
                MMA(s[nt], ql[kc], bh0, bh1);
            }
        }

        // ---- masked exp (log2 domain, no max subtraction), pack P frags ----
        u64 m0 = mr0[k0 >> 6];
        u64 m1 = mr1[k0 >> 6];
        u32 ph[8], ph2[8], pl[8], pl2[8];
        #pragma unroll
        for (int nt = 0; nt < 8; nt++) {
            int pos = nt * 8 + q4 * 2;
            float p0 = ((m0 >> pos)       & 1) ? ex2f(s[nt][0]) : 0.f;
            float p1 = ((m0 >> (pos + 1)) & 1) ? ex2f(s[nt][1]) : 0.f;
            float p2 = ((m1 >> pos)       & 1) ? ex2f(s[nt][2]) : 0.f;
            float p3 = ((m1 >> (pos + 1)) & 1) ? ex2f(s[nt][3]) : 0.f;
            l0 += p0 + p1;
            l1 += p2 + p3;
            split2(p0, p1, ph[nt],  pl[nt]);
            split2(p2, p3, ph2[nt], pl2[nt]);
        }

        // ---- O += P V ----
        #pragma unroll
        for (int tt = 0; tt < 4; tt++) {
            u32 ah[4] = {ph[2*tt], ph2[2*tt], ph[2*tt+1], ph2[2*tt+1]};
            u32 al[4] = {pl[2*tt], pl2[2*tt], pl[2*tt+1], pl2[2*tt+1]};
            #pragma unroll
            for (int nt = 0; nt < 8; nt++) {
                int rowV = nt * 8 + gq;
                int cc = tt * 16 + q4 * 2;
                u32 bh0 = *(const u32*)&Vth[rowV * KPAD + cc];
                u32 bh1 = *(const u32*)&Vth[rowV * KPAD + cc + 8];
                u32 bl0 = *(const u32*)&Vtl[rowV * KPAD + cc];
                u32 bl1 = *(const u32*)&Vtl[rowV * KPAD + cc + 8];
                MMA(o[nt], ah, bh0, bh1);
                MMA(o[nt], ah, bl0, bl1);
                MMA(o[nt], al, bh0, bh1);
            }
        }
    }

    // ---- epilogue: reduce l across the 4 lanes sharing each row, write ----
    l0 += __shfl_xor_sync(0xffffffffu, l0, 1);
    l0 += __shfl_xor_sync(0xffffffffu, l0, 2);
    l1 += __shfl_xor_sync(0xffffffffu, l1, 1);
    l1 += __shfl_xor_sync(0xffffffffu, l1, 2);
    float inv0 = 1.f / l0, inv1 = 1.f / l1;

    #pragma unroll
    for (int nt = 0; nt < 8; nt++) {
        int d = h * DKK + nt * 8 + q4 * 2;
        float2 a = make_float2(o[nt][0] * inv0, o[nt][1] * inv0);
        float2 c = make_float2(o[nt][2] * inv1, o[nt][3] * inv1);
        *(float2*)&g_C[((size_t)(b * NN) + r0    ) * EE + d] = a;
        *(float2*)&g_C[((size_t)(b * NN) + r0 + 8) * EE + d] = c;
    }
}

// ---------------------------------------------------------------------------
// Kernel C0: transpose Wo (R3 version).
// ---------------------------------------------------------------------------
__global__ void __launch_bounds__(256) wot_kernel(const float* __restrict__ Wo)
{
    int idx = blockIdx.x * 256 + threadIdx.x;
    int o = idx >> 8, d = idx & 255;
    g_WoT[d * EE + o] = Wo[idx];
}

// ---------------------------------------------------------------------------
// Kernel C: out = concat @ Wo^T + bo (R3 version).
// ---------------------------------------------------------------------------
__global__ void __launch_bounds__(256) out_kernel(
    const float* __restrict__ bo, float* __restrict__ out)
{
    __shared__ float cs[8][EE];
    const int m0 = blockIdx.x * 8;
    const int t  = threadIdx.x;

    for (int i = t * 4; i < 8 * EE; i += 256 * 4) {
        int r = i >> 8, d = i & 255;
        *(float4*)&cs[r][d] = *(const float4*)&g_C[(size_t)(m0 + r) * EE + d];
    }
    __syncthreads();

    float acc[8] = {0.f, 0.f, 0.f, 0.f, 0.f, 0.f, 0.f, 0.f};
    #pragma unroll 2
    for (int d = 0; d < EE; d++) {
        float wv = g_WoT[d * EE + t];
        #pragma unroll
        for (int r = 0; r < 8; r++) acc[r] = fmaf(cs[r][d], wv, acc[r]);
    }
    float bv = bo[t];
    #pragma unroll
    for (int r = 0; r < 8; r++)
        out[(size_t)(m0 + r) * EE + t] = acc[r] + bv;
}

// ---------------------------------------------------------------------------
extern "C" void kernel_launch(void* const* d_in, const int* in_sizes, int n_in,
                              void* d_out, int out_size)
{
    const float* X   = (const float*)d_in[0];
    const int*   Adj = (const int*)  d_in[1];
    const float* Wq  = (const float*)d_in[2];
    const float* Wk  = (const float*)d_in[3];
    const float* Wv  = (const float*)d_in[4];
    const float* Wo  = (const float*)d_in[5];
    const float* bo  = (const float*)d_in[6];
    float* out = (float*)d_out;

    mask_kernel<<<BB*NN*NN/32/8, 256>>>(Adj);
    qkv_kernel<<<MTOT / 8, 256>>>(X, Wq, Wk, Wv);
    wot_kernel<<<EE * EE / 256, 256>>>(Wo);
    attn_kernel<<<dim3(NN / 128, BB * HH), 256>>>();
    out_kernel<<<MTOT / 8, 256>>>(bo, out);
}

// round 6
// speedup vs baseline: 3.5581x; 1.7629x over previous
#include <cuda_runtime.h>
#include <cuda_bf16.h>
#include <math.h>
#include <stdint.h>
#include <stddef.h>

#define BB 2
#define NN 2048
#define EE 256
#define HH 4
#define DKK 64
#define MTOT (BB*NN)

// 1/sqrt(64) * log2(e): scores produced in log2 domain for ex2-softmax
#define QSCALE 0.1803368801111204f

typedef unsigned int u32;
typedef unsigned long long u64;

__device__ __forceinline__ float ex2f(float x) {
    float r; asm("ex2.approx.f32 %0, %1;" : "=f"(r) : "f"(x)); return r;
}
__device__ __forceinline__ u32 sptr(const void* p) {
    return (u32)__cvta_generic_to_shared(p);
}
__device__ __forceinline__ void ldsm4(u32& r0, u32& r1, u32& r2, u32& r3, u32 a) {
    asm volatile("ldmatrix.sync.aligned.m8n8.x4.shared.b16 {%0,%1,%2,%3}, [%4];"
        : "=r"(r0), "=r"(r1), "=r"(r2), "=r"(r3) : "r"(a));
}
__device__ __forceinline__ void ldsm4t(u32& r0, u32& r1, u32& r2, u32& r3, u32 a) {
    asm volatile("ldmatrix.sync.aligned.m8n8.x4.trans.shared.b16 {%0,%1,%2,%3}, [%4];"
        : "=r"(r0), "=r"(r1), "=r"(r2), "=r"(r3) : "r"(a));
}

// Scratch
__device__ float g_Q[BB*HH*NN*DKK];
__device__ __nv_bfloat16 g_Kh[BB*HH*NN*DKK], g_Kl[BB*HH*NN*DKK];
__device__ __nv_bfloat16 g_Vh[BB*HH*NN*DKK], g_Vl[BB*HH*NN*DKK];
__device__ float g_C[BB*NN*EE];
__device__ float g_WoT[EE*EE];
__device__ u32   g_mask[BB*NN*NN/32];   // adjacency bitmask, 1 MB

// bf16 hi/lo split of a pair of floats (used for Q and P fragments)
__device__ __forceinline__ void split2(float x, float y, u32& hi, u32& lo) {
    __nv_bfloat16 hx = __float2bfloat16(x), hy = __float2bfloat16(y);
    float rx = x - __bfloat162float(hx);
    float ry = y - __bfloat162float(hy);
    __nv_bfloat162 H = __halves2bfloat162(hx, hy);
    __nv_bfloat162 L = __halves2bfloat162(__float2bfloat16(rx), __float2bfloat16(ry));
    hi = *(u32*)&H; lo = *(u32*)&L;
}

#define MMA(d, a, b0_, b1_) asm volatile( \
    "mma.sync.aligned.m16n8k16.row.col.f32.bf16.bf16.f32 " \
    "{%0,%1,%2,%3}, {%4,%5,%6,%7}, {%8,%9}, {%0,%1,%2,%3};" \
    : "+f"(d[0]), "+f"(d[1]), "+f"(d[2]), "+f"(d[3]) \
    : "r"(a[0]), "r"(a[1]), "r"(a[2]), "r"(a[3]), "r"(b0_), "r"(b1_))

// ---------------------------------------------------------------------------
// Adjacency -> bitmask (ballot).
// ---------------------------------------------------------------------------
__global__ void __launch_bounds__(256) mask_kernel(const int* __restrict__ Adj)
{
    int gid  = blockIdx.x * 256 + threadIdx.x;
    int word = gid >> 5, lane = gid & 31;
    int v = Adj[(size_t)word * 32 + lane];
    u32 m = __ballot_sync(0xffffffffu, v > 0);
    if (lane == 0) g_mask[word] = m;
}

// ---------------------------------------------------------------------------
// Kernel A: fused Q/K/V projection; emits fp32 Q (pre-scaled) and bf16 hi/lo
// K and V so the attention hot loop never converts.
// ---------------------------------------------------------------------------
__global__ void __launch_bounds__(256) qkv_kernel(
    const float* __restrict__ X, const float* __restrict__ Wq,
    const float* __restrict__ Wk, const float* __restrict__ Wv)
{
    __shared__ float xs[8][EE];
    const int m0 = blockIdx.x * 8;
    const int t  = threadIdx.x;

    for (int i = t * 4; i < 8 * EE; i += 256 * 4) {
        int r = i >> 8, d = i & 255;
        *(float4*)&xs[r][d] = *(const float4*)&X[(size_t)(m0 + r) * EE + d];
    }
    __syncthreads();

    const int h = t >> 6, e = t & 63;
    const float* wq = Wq + (size_t)h * EE * DKK + e;
    const float* wk = Wk + (size_t)h * EE * DKK + e;
    const float* wv = Wv + (size_t)h * EE * DKK + e;

    float aq[8], ak[8], av[8];
    #pragma unroll
    for (int r = 0; r < 8; r++) { aq[r] = 0.f; ak[r] = 0.f; av[r] = 0.f; }

    #pragma unroll 2
    for (int d = 0; d < EE; d++) {
        float q_ = wq[d * DKK];
        float k_ = wk[d * DKK];
        float v_ = wv[d * DKK];
        #pragma unroll
        for (int r = 0; r < 8; r++) {
            float x_ = xs[r][d];
            aq[r] = fmaf(x_, q_, aq[r]);
            ak[r] = fmaf(x_, k_, ak[r]);
            av[r] = fmaf(x_, v_, av[r]);
        }
    }

    #pragma unroll
    for (int r = 0; r < 8; r++) {
        int m = m0 + r;
        int b = m >> 11, n = m & 2047;
        size_t base = ((size_t)(b * HH + h) * NN + n) * DKK + e;
        g_Q[base] = aq[r] * QSCALE;
        __nv_bfloat16 kh = __float2bfloat16(ak[r]);
        g_Kh[base] = kh;
        g_Kl[base] = __float2bfloat16(ak[r] - __bfloat162float(kh));
        __nv_bfloat16 vh = __float2bfloat16(av[r]);
        g_Vh[base] = vh;
        g_Vl[base] = __float2bfloat16(av[r] - __bfloat162float(vh));
    }
}

// ---------------------------------------------------------------------------
// Kernel B: flash attention, tensor cores + ldmatrix.
// Block = 128 thr (4 warps), warp w owns q rows [q0+w*16, +16). TQ=64, TK=64.
// Grid = (NN/64, B*H) = (32, 8) = 256 CTAs.
// Smem: Kh/Kl/Vh/Vl row-major [key][d], rows padded to 72 bf16 ->
// ldmatrix conflict-free (row stride 144B = 36 words -> 8 rows cover 32 banks).
//   S : B frags via ldmatrix.x4 (non-trans) on K rows.
//   PV: B frags via ldmatrix.x4.trans on V rows (transpose in the LSU).
// Softmax: static-offset ex2 in log2 domain, mask via precomputed bitmask,
// per-thread l accumulation (no max, no rescale, no in-loop shuffles).
// ---------------------------------------------------------------------------
#define KPAD 72

__global__ void __launch_bounds__(128) attn_kernel()
{
    __shared__ __nv_bfloat16 Kh[64*KPAD], Kl[64*KPAD];
    __shared__ __nv_bfloat16 Vh[64*KPAD], Vl[64*KPAD];

    const int t = threadIdx.x;
    const int w = t >> 5, lane = t & 31;
    const int gq = lane >> 2;      // row-in-frag 0..7
    const int q4 = lane & 3;       // col group
    const int q0 = blockIdx.x * 64;
    const int bh = blockIdx.y;
    const int b  = bh >> 2, h = bh & 3;

    const int r0 = q0 + w * 16 + gq;   // this thread's rows: r0, r0+8

    // ---- Q fragments in registers (hi/lo bf16), all 4 k-chunks ----
    u32 qh[4][4], ql[4][4];
    {
        const float* Qb = g_Q + (size_t)bh * NN * DKK;
        #pragma unroll
        for (int kc = 0; kc < 4; kc++) {
            int c = kc * 16 + q4 * 2;
            float2 x0 = *(const float2*)&Qb[(size_t)(r0    ) * DKK + c    ];
            float2 x1 = *(const float2*)&Qb[(size_t)(r0 + 8) * DKK + c    ];
            float2 x2 = *(const float2*)&Qb[(size_t)(r0    ) * DKK + c + 8];
            float2 x3 = *(const float2*)&Qb[(size_t)(r0 + 8) * DKK + c + 8];
            split2(x0.x, x0.y, qh[kc][0], ql[kc][0]);
            split2(x1.x, x1.y, qh[kc][1], ql[kc][1]);
            split2(x2.x, x2.y, qh[kc][2], ql[kc][2]);
            split2(x3.x, x3.y, qh[kc][3], ql[kc][3]);
        }
    }

    float o[8][4];
    #pragma unroll
    for (int nt = 0; nt < 8; nt++)
        #pragma unroll
        for (int j = 0; j < 4; j++) o[nt][j] = 0.f;
    float l0 = 0.f, l1 = 0.f;

    const u64* mr0 = (const u64*)g_mask + ((size_t)(b * NN + r0    )) * (NN / 64);
    const u64* mr1 = (const u64*)g_mask + ((size_t)(b * NN + r0 + 8)) * (NN / 64);

    // per-thread ldmatrix row-address offsets (bytes)
    const u32 KhB = sptr(Kh), KlB = sptr(Kl), VhB = sptr(Vh), VlB = sptr(Vl);
    const u32 offS = (u32)(((lane & 7) + ((lane >> 4) << 3)) * (KPAD * 2)
                           + (((lane >> 3) & 1) << 4));
    const u32 offV = (u32)(((lane & 7) + (((lane >> 3) & 1) << 3)) * (KPAD * 2)
                           + (((lane >> 4) & 1) << 4));

    for (int k0 = 0; k0 < NN; k0 += 64) {
        __syncthreads();   // previous tile fully consumed

        // ---- fill: pure float4 copies of precomputed bf16 tiles ----
        {
            const __nv_bfloat16* pKh = g_Kh + ((size_t)bh * NN + k0) * DKK;
            const __nv_bfloat16* pKl = g_Kl + ((size_t)bh * NN + k0) * DKK;
            const __nv_bfloat16* pVh = g_Vh + ((size_t)bh * NN + k0) * DKK;
            const __nv_bfloat16* pVl = g_Vl + ((size_t)bh * NN + k0) * DKK;
            #pragma unroll
            for (int i8 = t * 8; i8 < 64 * DKK; i8 += 128 * 8) {
                int row = i8 >> 6, col = i8 & 63;
                int so = row * KPAD + col;
                *(float4*)&Kh[so] = *(const float4*)&pKh[i8];
                *(float4*)&Kl[so] = *(const float4*)&pKl[i8];
                *(float4*)&Vh[so] = *(const float4*)&pVh[i8];
                *(float4*)&Vl[so] = *(const float4*)&pVl[i8];
            }
        }
        __syncthreads();

        // ---- S = Q K^T ----
        float s[8][4];
        #pragma unroll
        for (int nt = 0; nt < 8; nt++)
            #pragma unroll
            for (int j = 0; j < 4; j++) s[nt][j] = 0.f;

        #pragma unroll
        for (int kc = 0; kc < 4; kc++) {
            #pragma unroll
            for (int ntp = 0; ntp < 4; ntp++) {
                u32 a0, a1, a2, a3, c0, c1, c2, c3;
                u32 ad = offS + (u32)(ntp * 16 * KPAD * 2 + kc * 32);
                ldsm4(a0, a1, a2, a3, KhB + ad);
                ldsm4(c0, c1, c2, c3, KlB + ad);
                MMA(s[2*ntp],     qh[kc], a0, a1);
                MMA(s[2*ntp],     qh[kc], c0, c1);
                MMA(s[2*ntp],     ql[kc], a0, a1);
                MMA(s[2*ntp + 1], qh[kc], a2, a3);
                MMA(s[2*ntp + 1], qh[kc], c2, c3);
                MMA(s[2*ntp + 1], ql[kc], a2, a3);
            }
        }

        // ---- masked exp (log2 domain), pack P fragments ----
        u64 m0 = mr0[k0 >> 6];
        u64 m1 = mr1[k0 >> 6];
        u32 ph[8], ph2[8], pl[8], pl2[8];
        #pragma unroll
        for (int nt = 0; nt < 8; nt++) {
            int pos = nt * 8 + q4 * 2;
            float p0 = ((m0 >> pos)       & 1) ? ex2f(s[nt][0]) : 0.f;
            float p1 = ((m0 >> (pos + 1)) & 1) ? ex2f(s[nt][1]) : 0.f;
            float p2 = ((m1 >> pos)       & 1) ? ex2f(s[nt][2]) : 0.f;
            float p3 = ((m1 >> (pos + 1)) & 1) ? ex2f(s[nt][3]) : 0.f;
            l0 += p0 + p1;
            l1 += p2 + p3;
            split2(p0, p1, ph[nt],  pl[nt]);
            split2(p2, p3, ph2[nt], pl2[nt]);
        }

        // ---- O += P V ----
        #pragma unroll
        for (int tt = 0; tt < 4; tt++) {
            u32 ah[4] = {ph[2*tt], ph2[2*tt], ph[2*tt+1], ph2[2*tt+1]};
            u32 al[4] = {pl[2*tt], pl2[2*tt], pl[2*tt+1], pl2[2*tt+1]};
            #pragma unroll
            for (int ntp = 0; ntp < 4; ntp++) {
                u32 h0, h1, h2, h3, e0, e1, e2, e3;
                u32 ad = offV + (u32)(tt * 16 * KPAD * 2 + ntp * 32);
                ldsm4t(h0, h1, h2, h3, VhB + ad);
                ldsm4t(e0, e1, e2, e3, VlB + ad);
                MMA(o[2*ntp],     ah, h0, h1);
                MMA(o[2*ntp],     ah, e0, e1);
                MMA(o[2*ntp],     al, h0, h1);
                MMA(o[2*ntp + 1], ah, h2, h3);
                MMA(o[2*ntp + 1], ah, e2, e3);
                MMA(o[2*ntp + 1], al, h2, h3);
            }
        }
    }

    // ---- epilogue: reduce l across the 4 lanes sharing each row, write ----
    l0 += __shfl_xor_sync(0xffffffffu, l0, 1);
    l0 += __shfl_xor_sync(0xffffffffu, l0, 2);
    l1 += __shfl_xor_sync(0xffffffffu, l1, 1);
    l1 += __shfl_xor_sync(0xffffffffu, l1, 2);
    float inv0 = 1.f / l0, inv1 = 1.f / l1;

    #pragma unroll
    for (int nt = 0; nt < 8; nt++) {
        int d = h * DKK + nt * 8 + q4 * 2;
        float2 a = make_float2(o[nt][0] * inv0, o[nt][1] * inv0);
        float2 c = make_float2(o[nt][2] * inv1, o[nt][3] * inv1);
        *(float2*)&g_C[((size_t)(b * NN) + r0    ) * EE + d] = a;
        *(float2*)&g_C[((size_t)(b * NN) + r0 + 8) * EE + d] = c;
    }
}

// ---------------------------------------------------------------------------
// Kernel C0: transpose Wo.
// ---------------------------------------------------------------------------
__global__ void __launch_bounds__(256) wot_kernel(const float* __restrict__ Wo)
{
    int idx = blockIdx.x * 256 + threadIdx.x;
    int o = idx >> 8, d = idx & 255;
    g_WoT[d * EE + o] = Wo[idx];
}

// ---------------------------------------------------------------------------
// Kernel C: out = concat @ Wo^T + bo.
// ---------------------------------------------------------------------------
__global__ void __launch_bounds__(256) out_kernel(
    const float* __restrict__ bo, float* __restrict__ out)
{
    __shared__ float cs[8][EE];
    const int m0 = blockIdx.x * 8;
    const int t  = threadIdx.x;

    for (int i = t * 4; i < 8 * EE; i += 256 * 4) {
        int r = i >> 8, d = i & 255;
        *(float4*)&cs[r][d] = *(const float4*)&g_C[(size_t)(m0 + r) * EE + d];
    }
    __syncthreads();

    float acc[8] = {0.f, 0.f, 0.f, 0.f, 0.f, 0.f, 0.f, 0.f};
    #pragma unroll 2
    for (int d = 0; d < EE; d++) {
        float wv = g_WoT[d * EE + t];
        #pragma unroll
        for (int r = 0; r < 8; r++) acc[r] = fmaf(cs[r][d], wv, acc[r]);
    }
    float bv = bo[t];
    #pragma unroll
    for (int r = 0; r < 8; r++)
        out[(size_t)(m0 + r) * EE + t] = acc[r] + bv;
}

// ---------------------------------------------------------------------------
extern "C" void kernel_launch(void* const* d_in, const int* in_sizes, int n_in,
                              void* d_out, int out_size)
{
    const float* X   = (const float*)d_in[0];
    const int*   Adj = (const int*)  d_in[1];
    const float* Wq  = (const float*)d_in[2];
    const float* Wk  = (const float*)d_in[3];
    const float* Wv  = (const float*)d_in[4];
    const float* Wo  = (const float*)d_in[5];
    const float* bo  = (const float*)d_in[6];
    float* out = (float*)d_out;

    mask_kernel<<<BB*NN*NN/32/8, 256>>>(Adj);
    qkv_kernel<<<MTOT / 8, 256>>>(X, Wq, Wk, Wv);
    wot_kernel<<<EE * EE / 256, 256>>>(Wo);
    attn_kernel<<<dim3(NN / 64, BB * HH), 128>>>();
    out_kernel<<<MTOT / 8, 256>>>(bo, out);
}

// round 7
// speedup vs baseline: 4.8154x; 1.3534x over previous
#include <cuda_runtime.h>
#include <cuda_bf16.h>
#include <math.h>
#include <stdint.h>
#include <stddef.h>

#define BB 2
#define NN 2048
#define EE 256
#define HH 4
#define DKK 64
#define MTOT (BB*NN)

// 1/sqrt(64) * log2(e): scores produced in log2 domain for ex2-softmax
#define QSCALE 0.1803368801111204f

typedef unsigned int u32;
typedef unsigned long long u64;

__device__ __forceinline__ float ex2f(float x) {
    float r; asm("ex2.approx.f32 %0, %1;" : "=f"(r) : "f"(x)); return r;
}
__device__ __forceinline__ u32 sptr(const void* p) {
    return (u32)__cvta_generic_to_shared(p);
}
__device__ __forceinline__ void ldsm4(u32& r0, u32& r1, u32& r2, u32& r3, u32 a) {
    asm volatile("ldmatrix.sync.aligned.m8n8.x4.shared.b16 {%0,%1,%2,%3}, [%4];"
        : "=r"(r0), "=r"(r1), "=r"(r2), "=r"(r3) : "r"(a));
}
__device__ __forceinline__ void ldsm4t(u32& r0, u32& r1, u32& r2, u32& r3, u32 a) {
    asm volatile("ldmatrix.sync.aligned.m8n8.x4.trans.shared.b16 {%0,%1,%2,%3}, [%4];"
        : "=r"(r0), "=r"(r1), "=r"(r2), "=r"(r3) : "r"(a));
}

// Scratch: everything the hot kernels touch is pre-split bf16 hi/lo.
__device__ __nv_bfloat16 g_Xh[MTOT*EE],  g_Xl[MTOT*EE];     // X split
__device__ __nv_bfloat16 g_Wh[12*DKK*EE], g_Wl[12*DKK*EE];  // Wq/Wk/Wv transposed+split
__device__ __nv_bfloat16 g_Woh[EE*EE],   g_Wol[EE*EE];      // Wo split (rows d-contig)
__device__ __nv_bfloat16 g_Qh[BB*HH*NN*DKK], g_Ql[BB*HH*NN*DKK];
__device__ __nv_bfloat16 g_Kh[BB*HH*NN*DKK], g_Kl[BB*HH*NN*DKK];
__device__ __nv_bfloat16 g_Vh[BB*HH*NN*DKK], g_Vl[BB*HH*NN*DKK];
__device__ __nv_bfloat16 g_Ch[MTOT*EE],  g_Cl[MTOT*EE];     // attn output split
__device__ u32 g_mask[BB*NN*NN/32];                          // adjacency bitmask

// bf16 hi/lo split of a pair of floats
__device__ __forceinline__ void split2(float x, float y, u32& hi, u32& lo) {
    __nv_bfloat16 hx = __float2bfloat16(x), hy = __float2bfloat16(y);
    float rx = x - __bfloat162float(hx);
    float ry = y - __bfloat162float(hy);
    __nv_bfloat162 H = __halves2bfloat162(hx, hy);
    __nv_bfloat162 L = __halves2bfloat162(__float2bfloat16(rx), __float2bfloat16(ry));
    hi = *(u32*)&H; lo = *(u32*)&L;
}

#define MMA(d, a, b0_, b1_) asm volatile( \
    "mma.sync.aligned.m16n8k16.row.col.f32.bf16.bf16.f32 " \
    "{%0,%1,%2,%3}, {%4,%5,%6,%7}, {%8,%9}, {%0,%1,%2,%3};" \
    : "+f"(d[0]), "+f"(d[1]), "+f"(d[2]), "+f"(d[3]) \
    : "r"(a[0]), "r"(a[1]), "r"(a[2]), "r"(a[3]), "r"(b0_), "r"(b1_))

// ---------------------------------------------------------------------------
// Prep: adjacency bitmask.
// ---------------------------------------------------------------------------
__global__ void __launch_bounds__(256) mask_kernel(const int* __restrict__ Adj)
{
    int gid  = blockIdx.x * 256 + threadIdx.x;
    int word = gid >> 5, lane = gid & 31;
    int v = Adj[(size_t)word * 32 + lane];
    u32 m = __ballot_sync(0xffffffffu, v > 0);
    if (lane == 0) g_mask[word] = m;
}

// ---------------------------------------------------------------------------
// Prep: split X into bf16 hi/lo.
// ---------------------------------------------------------------------------
__global__ void __launch_bounds__(256) xsplit_kernel(const float* __restrict__ X)
{
    int i = (blockIdx.x * 256 + threadIdx.x) * 4;
    float4 v = *(const float4*)&X[i];
    u32 h0, l0, h1, l1;
    split2(v.x, v.y, h0, l0);
    split2(v.z, v.w, h1, l1);
    *(u32*)&g_Xh[i]     = h0; *(u32*)&g_Xh[i + 2] = h1;
    *(u32*)&g_Xl[i]     = l0; *(u32*)&g_Xl[i + 2] = l1;
}

// ---------------------------------------------------------------------------
// Prep: transpose + split Wq/Wk/Wv -> g_Wh/g_Wl rows (mat*4+h)*64+e, cols d.
// ---------------------------------------------------------------------------
__global__ void __launch_bounds__(256) wsplit_kernel(
    const float* __restrict__ Wq, const float* __restrict__ Wk,
    const float* __restrict__ Wv)
{
    int idx = blockIdx.x * 256 + threadIdx.x;      // [0, 196608)
    int mat = idx >> 16;
    int rem = idx & 65535;                          // h*16384 + d*64 + e
    const float* src = (mat == 0) ? Wq : (mat == 1) ? Wk : Wv;
    int h = rem >> 14, d = (rem >> 6) & 255, e = rem & 63;
    float v = src[rem];
    __nv_bfloat16 hi = __float2bfloat16(v);
    size_t dst = (size_t)((mat * HH + h) * DKK + e) * EE + d;
    g_Wh[dst] = hi;
    g_Wl[dst] = __float2bfloat16(v - __bfloat162float(hi));
}

// ---------------------------------------------------------------------------
// Prep: split Wo (already d-contiguous per output row).
// ---------------------------------------------------------------------------
__global__ void __launch_bounds__(256) wosplit_kernel(const float* __restrict__ Wo)
{
    int idx = blockIdx.x * 256 + threadIdx.x;      // o*256 + d
    float v = Wo[idx];
    __nv_bfloat16 hi = __float2bfloat16(v);
    g_Woh[idx] = hi;
    g_Wol[idx] = __float2bfloat16(v - __bfloat162float(hi));
}

// ---------------------------------------------------------------------------
// Tensor-core QKV projection: out[m, (mat,h,e)] = sum_d X[m,d] W[mat,h,d,e].
// M=4096, N=768 (12 blocks of 64, each one (mat,h)), K=256.
// Block = 128 thr (4 warps, warp owns 16 rows x 64 cols). 3-term bf16 mma.
// Epilogue writes Q/K/V split hi/lo (QSCALE folded into Q).
// ---------------------------------------------------------------------------
#define KPAD 72

__global__ void __launch_bounds__(128) qkv_mma_kernel()
{
    __shared__ __nv_bfloat16 Ah[64*KPAD], Al[64*KPAD];
    __shared__ __nv_bfloat16 Bh[64*KPAD], Bl[64*KPAD];

    const int t = threadIdx.x;
    const int w = t >> 5, lane = t & 31;
    const int gq = lane >> 2, q4 = lane & 3;
    const int m0 = blockIdx.x * 64;
    const int n0 = blockIdx.y * 64;

    float acc[8][4];
    #pragma unroll
    for (int nt = 0; nt < 8; nt++)
        #pragma unroll
        for (int j = 0; j < 4; j++) acc[nt][j] = 0.f;

    const u32 AhB = sptr(Ah), AlB = sptr(Al), BhB = sptr(Bh), BlB = sptr(Bl);
    const u32 offA = (u32)(((lane & 7) + (((lane >> 3) & 1) << 3) + w * 16) * (KPAD * 2)
                           + (((lane >> 4) & 1) << 4));
    const u32 offB = (u32)(((lane & 7) + (((lane >> 4) & 1) << 3)) * (KPAD * 2)
                           + (((lane >> 3) & 1) << 4));

    for (int k0 = 0; k0 < EE; k0 += 64) {
        __syncthreads();
        #pragma unroll
        for (int i8 = t * 8; i8 < 64 * 64; i8 += 128 * 8) {
            int row = i8 >> 6, col = i8 & 63;
            int so = row * KPAD + col;
            *(float4*)&Ah[so] = *(const float4*)&g_Xh[(size_t)(m0 + row) * EE + k0 + col];
            *(float4*)&Al[so] = *(const float4*)&g_Xl[(size_t)(m0 + row) * EE + k0 + col];
            *(float4*)&Bh[so] = *(const float4*)&g_Wh[(size_t)(n0 + row) * EE + k0 + col];
            *(float4*)&Bl[so] = *(const float4*)&g_Wl[(size_t)(n0 + row) * EE + k0 + col];
        }
        __syncthreads();

        #pragma unroll
        for (int k16 = 0; k16 < 4; k16++) {
            u32 ah[4], al[4];
            ldsm4(ah[0], ah[1], ah[2], ah[3], AhB + offA + k16 * 32);
            ldsm4(al[0], al[1], al[2], al[3], AlB + offA + k16 * 32);
            #pragma unroll
            for (int ntp = 0; ntp < 4; ntp++) {
                u32 b0, b1, b2, b3, c0, c1, c2, c3;
                u32 ad = offB + (u32)(ntp * 16 * KPAD * 2 + k16 * 32);
                ldsm4(b0, b1, b2, b3, BhB + ad);
                ldsm4(c0, c1, c2, c3, BlB + ad);
                MMA(acc[2*ntp],     ah, b0, b1);
                MMA(acc[2*ntp],     ah, c0, c1);
                MMA(acc[2*ntp],     al, b0, b1);
                MMA(acc[2*ntp + 1], ah, b2, b3);
                MMA(acc[2*ntp + 1], ah, c2, c3);
                MMA(acc[2*ntp + 1], al, b2, b3);
            }
        }
    }

    const int mat = n0 >> 8, h = (n0 >> 6) & 3;
    __nv_bfloat16* dh = (mat == 0) ? g_Qh : (mat == 1) ? g_Kh : g_Vh;
    __nv_bfloat16* dl = (mat == 0) ? g_Ql : (mat == 1) ? g_Kl : g_Vl;
    const float mult = (mat == 0) ? QSCALE : 1.0f;

    const int r0 = m0 + w * 16 + gq;
    const int b0_ = r0 >> 11, n2_0 = r0 & 2047;
    const int b1_ = (r0 + 8) >> 11, n2_1 = (r0 + 8) & 2047;
    #pragma unroll
    for (int nt = 0; nt < 8; nt++) {
        int c = nt * 8 + q4 * 2;
        u32 hi, lo;
        split2(acc[nt][0] * mult, acc[nt][1] * mult, hi, lo);
        size_t a0 = ((size_t)((b0_ * HH + h) * NN + n2_0)) * DKK + c;
        *(u32*)&dh[a0] = hi; *(u32*)&dl[a0] = lo;
        split2(acc[nt][2] * mult, acc[nt][3] * mult, hi, lo);
        size_t a1 = ((size_t)((b1_ * HH + h) * NN + n2_1)) * DKK + c;
        *(u32*)&dh[a1] = hi; *(u32*)&dl[a1] = lo;
    }
}

// ---------------------------------------------------------------------------
// Flash attention (unchanged structure from R6; Q now pre-split in global,
// epilogue writes C split hi/lo for the mma output projection).
// ---------------------------------------------------------------------------
__global__ void __launch_bounds__(128) attn_kernel()
{
    __shared__ __nv_bfloat16 Kh[64*KPAD], Kl[64*KPAD];
    __shared__ __nv_bfloat16 Vh[64*KPAD], Vl[64*KPAD];

    const int t = threadIdx.x;
    const int w = t >> 5, lane = t & 31;
    const int gq = lane >> 2, q4 = lane & 3;
    const int q0 = blockIdx.x * 64;
    const int bh = blockIdx.y;
    const int b  = bh >> 2, h = bh & 3;

    const int r0 = q0 + w * 16 + gq;

    // ---- Q fragments: direct bf16x2 loads from pre-split globals ----
    u32 qh[4][4], ql[4][4];
    {
        const __nv_bfloat16* Qh = g_Qh + (size_t)bh * NN * DKK;
        const __nv_bfloat16* Ql = g_Ql + (size_t)bh * NN * DKK;
        #pragma unroll
        for (int kc = 0; kc < 4; kc++) {
            int c = kc * 16 + q4 * 2;
            qh[kc][0] = *(const u32*)&Qh[(size_t)(r0    ) * DKK + c    ];
            qh[kc][1] = *(const u32*)&Qh[(size_t)(r0 + 8) * DKK + c    ];
            qh[kc][2] = *(const u32*)&Qh[(size_t)(r0    ) * DKK + c + 8];
            qh[kc][3] = *(const u32*)&Qh[(size_t)(r0 + 8) * DKK + c + 8];
            ql[kc][0] = *(const u32*)&Ql[(size_t)(r0    ) * DKK + c    ];
            ql[kc][1] = *(const u32*)&Ql[(size_t)(r0 + 8) * DKK + c    ];
            ql[kc][2] = *(const u32*)&Ql[(size_t)(r0    ) * DKK + c + 8];
            ql[kc][3] = *(const u32*)&Ql[(size_t)(r0 + 8) * DKK + c + 8];
        }
    }

    float o[8][4];
    #pragma unroll
    for (int nt = 0; nt < 8; nt++)
        #pragma unroll
        for (int j = 0; j < 4; j++) o[nt][j] = 0.f;
    float l0 = 0.f, l1 = 0.f;

    const u64* mr0 = (const u64*)g_mask + ((size_t)(b * NN + r0    )) * (NN / 64);
    const u64* mr1 = (const u64*)g_mask + ((size_t)(b * NN + r0 + 8)) * (NN / 64);

    const u32 KhB = sptr(Kh), KlB = sptr(Kl), VhB = sptr(Vh), VlB = sptr(Vl);
    const u32 offS = (u32)(((lane & 7) + ((lane >> 4) << 3)) * (KPAD * 2)
                           + (((lane >> 3) & 1) << 4));
    const u32 offV = (u32)(((lane & 7) + (((lane >> 3) & 1) << 3)) * (KPAD * 2)
                           + (((lane >> 4) & 1) << 4));

    for (int k0 = 0; k0 < NN; k0 += 64) {
        __syncthreads();
        {
            const __nv_bfloat16* pKh = g_Kh + ((size_t)bh * NN + k0) * DKK;
            const __nv_bfloat16* pKl = g_Kl + ((size_t)bh * NN + k0) * DKK;
            const __nv_bfloat16* pVh = g_Vh + ((size_t)bh * NN + k0) * DKK;
            const __nv_bfloat16* pVl = g_Vl + ((size_t)bh * NN + k0) * DKK;
            #pragma unroll
            for (int i8 = t * 8; i8 < 64 * DKK; i8 += 128 * 8) {
                int row = i8 >> 6, col = i8 & 63;
                int so = row * KPAD + col;
                *(float4*)&Kh[so] = *(const float4*)&pKh[i8];
                *(float4*)&Kl[so] = *(const float4*)&pKl[i8];
                *(float4*)&Vh[so] = *(const float4*)&pVh[i8];
                *(float4*)&Vl[so] = *(const float4*)&pVl[i8];
            }
        }
        __syncthreads();

        // ---- S = Q K^T ----
        float s[8][4];
        #pragma unroll
        for (int nt = 0; nt < 8; nt++)
            #pragma unroll
            for (int j = 0; j < 4; j++) s[nt][j] = 0.f;

        #pragma unroll
        for (int kc = 0; kc < 4; kc++) {
            #pragma unroll
            for (int ntp = 0; ntp < 4; ntp++) {
                u32 a0, a1, a2, a3, c0, c1, c2, c3;
                u32 ad = offS + (u32)(ntp * 16 * KPAD * 2 + kc * 32);
                ldsm4(a0, a1, a2, a3, KhB + ad);
                ldsm4(c0, c1, c2, c3, KlB + ad);
                MMA(s[2*ntp],     qh[kc], a0, a1);
                MMA(s[2*ntp],     qh[kc], c0, c1);
                MMA(s[2*ntp],     ql[kc], a0, a1);
                MMA(s[2*ntp + 1], qh[kc], a2, a3);
                MMA(s[2*ntp + 1], qh[kc], c2, c3);
                MMA(s[2*ntp + 1], ql[kc], a2, a3);
            }
        }

        // ---- masked exp (log2 domain), pack P fragments ----
        u64 m0 = mr0[k0 >> 6];
        u64 m1 = mr1[k0 >> 6];
        u32 ph[8], ph2[8], pl[8], pl2[8];
        #pragma unroll
        for (int nt = 0; nt < 8; nt++) {
            int pos = nt * 8 + q4 * 2;
            float p0 = ((m0 >> pos)       & 1) ? ex2f(s[nt][0]) : 0.f;
            float p1 = ((m0 >> (pos + 1)) & 1) ? ex2f(s[nt][1]) : 0.f;
            float p2 = ((m1 >> pos)       & 1) ? ex2f(s[nt][2]) : 0.f;
            float p3 = ((m1 >> (pos + 1)) & 1) ? ex2f(s[nt][3]) : 0.f;
            l0 += p0 + p1;
            l1 += p2 + p3;
            split2(p0, p1, ph[nt],  pl[nt]);
            split2(p2, p3, ph2[nt], pl2[nt]);
        }

        // ---- O += P V ----
        #pragma unroll
        for (int tt = 0; tt < 4; tt++) {
            u32 ah[4] = {ph[2*tt], ph2[2*tt], ph[2*tt+1], ph2[2*tt+1]};
            u32 al[4] = {pl[2*tt], pl2[2*tt], pl[2*tt+1], pl2[2*tt+1]};
            #pragma unroll
            for (int ntp = 0; ntp < 4; ntp++) {
                u32 h0, h1, h2, h3, e0, e1, e2, e3;
                u32 ad = offV + (u32)(tt * 16 * KPAD * 2 + ntp * 32);
                ldsm4t(h0, h1, h2, h3, VhB + ad);
                ldsm4t(e0, e1, e2, e3, VlB + ad);
                MMA(o[2*ntp],     ah, h0, h1);
                MMA(o[2*ntp],     ah, e0, e1);
                MMA(o[2*ntp],     al, h0, h1);
                MMA(o[2*ntp + 1], ah, h2, h3);
                MMA(o[2*ntp + 1], ah, e2, e3);
                MMA(o[2*ntp + 1], al, h2, h3);
            }
        }
    }

    // ---- epilogue: reduce l, split C into hi/lo bf16 ----
    l0 += __shfl_xor_sync(0xffffffffu, l0, 1);
    l0 += __shfl_xor_sync(0xffffffffu, l0, 2);
    l1 += __shfl_xor_sync(0xffffffffu, l1, 1);
    l1 += __shfl_xor_sync(0xffffffffu, l1, 2);
    float inv0 = 1.f / l0, inv1 = 1.f / l1;

    #pragma unroll
    for (int nt = 0; nt < 8; nt++) {
        int d = h * DKK + nt * 8 + q4 * 2;
        u32 hi, lo;
        split2(o[nt][0] * inv0, o[nt][1] * inv0, hi, lo);
        size_t a0 = ((size_t)(b * NN) + r0) * EE + d;
        *(u32*)&g_Ch[a0] = hi; *(u32*)&g_Cl[a0] = lo;
        split2(o[nt][2] * inv1, o[nt][3] * inv1, hi, lo);
        size_t a1 = ((size_t)(b * NN) + r0 + 8) * EE + d;
        *(u32*)&g_Ch[a1] = hi; *(u32*)&g_Cl[a1] = lo;
    }
}

// ---------------------------------------------------------------------------
// Tensor-core output projection: out = C @ Wo^T + bo. M=4096, N=256, K=256.
// ---------------------------------------------------------------------------
__global__ void __launch_bounds__(128) out_mma_kernel(
    const float* __restrict__ bo, float* __restrict__ out)
{
    __shared__ __nv_bfloat16 Ah[64*KPAD], Al[64*KPAD];
    __shared__ __nv_bfloat16 Bh[64*KPAD], Bl[64*KPAD];

    const int t = threadIdx.x;
    const int w = t >> 5, lane = t & 31;
    const int gq = lane >> 2, q4 = lane & 3;
    const int m0 = blockIdx.x * 64;
    const int n0 = blockIdx.y * 64;

    float acc[8][4];
    #pragma unroll
    for (int nt = 0; nt < 8; nt++)
        #pragma unroll
        for (int j = 0; j < 4; j++) acc[nt][j] = 0.f;

    const u32 AhB = sptr(Ah), AlB = sptr(Al), BhB = sptr(Bh), BlB = sptr(Bl);
    const u32 offA = (u32)(((lane & 7) + (((lane >> 3) & 1) << 3) + w * 16) * (KPAD * 2)
                           + (((lane >> 4) & 1) << 4));
    const u32 offB = (u32)(((lane & 7) + (((lane >> 4) & 1) << 3)) * (KPAD * 2)
                           + (((lane >> 3) & 1) << 4));

    for (int k0 = 0; k0 < EE; k0 += 64) {
        __syncthreads();
        #pragma unroll
        for (int i8 = t * 8; i8 < 64 * 64; i8 += 128 * 8) {
            int row = i8 >> 6, col = i8 & 63;
            int so = row * KPAD + col;
            *(float4*)&Ah[so] = *(const float4*)&g_Ch[(size_t)(m0 + row) * EE + k0 + col];
            *(float4*)&Al[so] = *(const float4*)&g_Cl[(size_t)(m0 + row) * EE + k0 + col];
            *(float4*)&Bh[so] = *(const float4*)&g_Woh[(size_t)(n0 + row) * EE + k0 + col];
            *(float4*)&Bl[so] = *(const float4*)&g_Wol[(size_t)(n0 + row) * EE + k0 + col];
        }
        __syncthreads();

        #pragma unroll
        for (int k16 = 0; k16 < 4; k16++) {
            u32 ah[4], al[4];
            ldsm4(ah[0], ah[1], ah[2], ah[3], AhB + offA + k16 * 32);
            ldsm4(al[0], al[1], al[2], al[3], AlB + offA + k16 * 32);
            #pragma unroll
            for (int ntp = 0; ntp < 4; ntp++) {
                u32 b0, b1, b2, b3, c0, c1, c2, c3;
                u32 ad = offB + (u32)(ntp * 16 * KPAD * 2 + k16 * 32);
                ldsm4(b0, b1, b2, b3, BhB + ad);
                ldsm4(c0, c1, c2, c3, BlB + ad);
                MMA(acc[2*ntp],     ah, b0, b1);
                MMA(acc[2*ntp],     ah, c0, c1);
                MMA(acc[2*ntp],     al, b0, b1);
                MMA(acc[2*ntp + 1], ah, b2, b3);
                MMA(acc[2*ntp + 1], ah, c2, c3);
                MMA(acc[2*ntp + 1], al, b2, b3);
            }
        }
    }

    const int r0 = m0 + w * 16 + gq;
    #pragma unroll
    for (int nt = 0; nt < 8; nt++) {
        int c = n0 + nt * 8 + q4 * 2;
        float2 bv = *(const float2*)&bo[c];
        float2 v0 = make_float2(acc[nt][0] + bv.x, acc[nt][1] + bv.y);
        float2 v1 = make_float2(acc[nt][2] + bv.x, acc[nt][3] + bv.y);
        *(float2*)&out[(size_t)(r0    ) * EE + c] = v0;
        *(float2*)&out[(size_t)(r0 + 8) * EE + c] = v1;
    }
}

// ---------------------------------------------------------------------------
extern "C" void kernel_launch(void* const* d_in, const int* in_sizes, int n_in,
                              void* d_out, int out_size)
{
    const float* X   = (const float*)d_in[0];
    const int*   Adj = (const int*)  d_in[1];
    const float* Wq  = (const float*)d_in[2];
    const float* Wk  = (const float*)d_in[3];
    const float* Wv  = (const float*)d_in[4];
    const float* Wo  = (const float*)d_in[5];
    const float* bo  = (const float*)d_in[6];
    float* out = (float*)d_out;

    mask_kernel<<<BB*NN*NN/256, 256>>>(Adj);
    xsplit_kernel<<<MTOT*EE/1024, 256>>>(X);
    wsplit_kernel<<<768, 256>>>(Wq, Wk, Wv);
    wosplit_kernel<<<256, 256>>>(Wo);
    qkv_mma_kernel<<<dim3(MTOT/64, 12), 128>>>();
    attn_kernel<<<dim3(NN/64, BB*HH), 128>>>();
    out_mma_kernel<<<dim3(MTOT/64, 4), 128>>>(bo, out);
}